// round 14
// baseline (speedup 1.0000x reference)
#include <cuda_runtime.h>
#include <cuda_fp16.h>
#include <cstdint>

typedef unsigned long long u64;
typedef uint32_t u32;

// Problem constants
#define O_N   512
#define T_N   1024
#define HW    256     // 16x16
#define DIN   64
#define DP    64
#define HID   128
#define DOUT  128

// ===========================================================================
// Side streams/events: created ONCE at program load (static initializer).
// ===========================================================================
struct SideRes {
    cudaStream_t s1, s2;
    cudaEvent_t  eP, eW, eC, e1, e2;
    SideRes() {
        cudaStreamCreateWithFlags(&s1, cudaStreamNonBlocking);
        cudaStreamCreateWithFlags(&s2, cudaStreamNonBlocking);
        cudaEventCreateWithFlags(&eP, cudaEventDisableTiming);
        cudaEventCreateWithFlags(&eW, cudaEventDisableTiming);
        cudaEventCreateWithFlags(&eC, cudaEventDisableTiming);
        cudaEventCreateWithFlags(&e1, cudaEventDisableTiming);
        cudaEventCreateWithFlags(&e2, cudaEventDisableTiming);
    }
};
static SideRes g_res;

// ===========================================================================
// mma.sync / ldmatrix / cp.async helpers
// ===========================================================================
__device__ __forceinline__ u32 smem_u32(const void* p) {
    u32 a;
    asm("{ .reg .u64 t; cvta.to.shared.u64 t, %1; cvt.u32.u64 %0, t; }" : "=r"(a) : "l"(p));
    return a;
}
__device__ __forceinline__ void ldsm4(u32* r, u32 addr) {
    asm volatile("ldmatrix.sync.aligned.m8n8.x4.shared.b16 {%0,%1,%2,%3}, [%4];"
                 : "=r"(r[0]), "=r"(r[1]), "=r"(r[2]), "=r"(r[3]) : "r"(addr));
}
__device__ __forceinline__ void mma16816(float* d, const u32* a, const u32* b) {
    asm volatile(
        "mma.sync.aligned.m16n8k16.row.col.f32.f16.f16.f32 "
        "{%0,%1,%2,%3}, {%4,%5,%6,%7}, {%8,%9}, {%0,%1,%2,%3};"
        : "+f"(d[0]), "+f"(d[1]), "+f"(d[2]), "+f"(d[3])
        : "r"(a[0]), "r"(a[1]), "r"(a[2]), "r"(a[3]), "r"(b[0]), "r"(b[1]));
}
__device__ __forceinline__ void cpa16(u32 dst, const void* src) {
    asm volatile("cp.async.cg.shared.global [%0], [%1], 16;" :: "r"(dst), "l"(src));
}
#define CP_COMMIT() asm volatile("cp.async.commit_group;" ::: "memory")
#define CP_WAIT0()  asm volatile("cp.async.wait_group 0;" ::: "memory")

// ===========================================================================
// Scratch buffers. All intermediates fp16 in [n][px(256)][ch(128)] layout.
// ===========================================================================
__device__ __align__(16) __half g_t1 [(size_t)T_N * HW * HID];
__device__ __align__(16) __half g_ys [(size_t)O_N * HW * HID];
__device__ __align__(16) __half g_yo [(size_t)O_N * HW * HID];
__device__ __align__(16) __half g_T1s[(size_t)O_N * HW * HID];
__device__ __align__(16) __half g_T1o[(size_t)O_N * HW * HID];
__device__ __align__(16) __half g_pooled[(size_t)O_N * HW * HID];
__device__ __align__(16) __half g_u  [(size_t)O_N * HW * HID];
__device__ __align__(16) __half g_v  [(size_t)O_N * HW * HID];
__device__ float g_yp [(size_t)T_N * HID * 9];
__device__ float g_wc [9 * HID * 64];
__device__ float g_cnt[2 * O_N];

// fp16 weights, padded tile layout (tile = tap*NCHUNK+chunk; [co][72 halfs])
__device__ __align__(16) __half g_was  [ 82944];
__device__ __align__(16) __half g_wao  [ 82944];
__device__ __align__(16) __half g_w1bp [165888];
__device__ __align__(16) __half g_w1bso[331776];
__device__ __align__(16) __half g_w2a  [165888];
__device__ __align__(16) __half g_w2b  [ 18432];
__device__ __align__(16) __half g_woa  [ 82944];
__device__ __align__(16) __half g_wob  [ 18432];

// ===========================================================================
// Mega weight prep
// ===========================================================================
struct PrepDesc {
    const float* W;
    __half* H;
    int co_off, ci_off, cin, ks2, nch, dst_ch0, dst_nch;
};
struct PrepTable { PrepDesc d[9]; };

__global__ void __launch_bounds__(256) megaprep(PrepTable tab)
{
    PrepDesc d = tab.d[blockIdx.y];
    const int per_co = d.ks2 * d.nch * 72;
    const int total  = 128 * per_co;
    for (int idx = blockIdx.x * blockDim.x + threadIdx.x; idx < total;
         idx += gridDim.x * blockDim.x) {
        int co   = idx / per_co;
        int rem  = idx % per_co;
        int t    = rem / (d.nch * 72);
        int rem2 = rem % (d.nch * 72);
        int ch   = rem2 / 72;
        int c72  = rem2 % 72;
        float v = 0.f;
        if (c72 < 64)
            v = d.W[((size_t)(co + d.co_off) * d.cin + d.ci_off + ch * 64 + c72) * d.ks2 + t];
        int tile = t * d.dst_nch + d.dst_ch0 + ch;
        d.H[(size_t)tile * 9216 + (size_t)co * 72 + c72] = __float2half_rn(v);
    }
}

// Wc[cls][co][ci]
__global__ void wc_kernel(const float* __restrict__ w1a, float* __restrict__ Wc) {
    int idx = blockIdx.x * blockDim.x + threadIdx.x;
    if (idx >= 9 * 128 * 64) return;
    int cls = idx / (128 * 64);
    int co  = (idx / 64) % 128;
    int ci  = idx % 64;
    int cy = cls / 3, cx = cls % 3;
    float sum = 0.f;
    for (int ky = 0; ky < 3; ky++) {
        if ((cy == 0 && ky == 0) || (cy == 2 && ky == 2)) continue;
        for (int kx = 0; kx < 3; kx++) {
            if ((cx == 0 && kx == 0) || (cx == 2 && kx == 2)) continue;
            sum += w1a[((size_t)co * 192 + 64 + ci) * 9 + ky * 3 + kx];
        }
    }
    Wc[idx] = sum;
}

// yp[t][co*9+cls]
__global__ void __launch_bounds__(256) yp_kernel(
    const float* __restrict__ pred, const float* __restrict__ Wc,
    float* __restrict__ yp)
{
    __shared__ float sp[64];
    int t = blockIdx.x;
    int tid = threadIdx.x;
    if (tid < 64) sp[tid] = pred[(size_t)t * DP + tid];
    __syncthreads();
    for (int i = tid; i < 128 * 9; i += 256) {
        int co = i / 9, cls = i % 9;
        const float* wc = Wc + ((size_t)cls * 128 + co) * 64;
        float sum = 0.f;
#pragma unroll 16
        for (int ci = 0; ci < 64; ci++) sum += sp[ci] * wc[ci];
        yp[(size_t)t * 1152 + i] = sum;
    }
}

// ===========================================================================
// Combine (fp16 in/out, [px][ch] layout): t1 = lrelu(inorm(ys[s]+yp+yo[o]))
// Grid (T_N, 2): 64-channel halves. Reduction order identical to prior round.
// ===========================================================================
#define CBH_VAL   0                       // 64*256 fp32
#define CBH_YP    16384
#define CBH_SUM   (16384 + 576)
#define CBH_SSQ   (16384 + 576 + 512)
#define CBH_MEAN  (16384 + 576 + 1024)
#define CBH_SCL   (16384 + 576 + 1024 + 64)
#define CBH_SMEM  ((16384 + 576 + 1024 + 128) * 4)

__global__ void __launch_bounds__(256) combine_h(
    const __half* __restrict__ ysh, const __half* __restrict__ yoh,
    const float* __restrict__ yp, const int* __restrict__ edges,
    __half* __restrict__ t1h)
{
    extern __shared__ float sm[];
    float* s_val  = sm + CBH_VAL;
    float* s_yp   = sm + CBH_YP;
    float* s_sum  = sm + CBH_SUM;
    float* s_ssq  = sm + CBH_SSQ;
    float* s_mean = sm + CBH_MEAN;
    float* s_scl  = sm + CBH_SCL;

    const int t   = blockIdx.x;
    const int hh  = blockIdx.y;
    const int tid = threadIdx.x;
    const int lane = tid & 31;
    const int w    = tid >> 5;
    const int s = edges[2 * t], o = edges[2 * t + 1];

    for (int i = tid; i < 576; i += 256)
        s_yp[i] = yp[(size_t)t * 1152 + hh * 576 + i];
    __syncthreads();

    const int px = tid;
    const int y = px >> 4, x = px & 15;
    const int cy = (y == 0) ? 0 : ((y == 15) ? 2 : 1);
    const int cx = (x == 0) ? 0 : ((x == 15) ? 2 : 1);
    const int cls = cy * 3 + cx;

    // bulk-load ys/yo rows (64 halfs each), fuse into s_val [ch][px]
    {
        const int4* ysrow = (const int4*)(ysh + ((size_t)s * HW + px) * HID + hh * 64);
        const int4* yorow = (const int4*)(yoh + ((size_t)o * HW + px) * HID + hh * 64);
#pragma unroll
        for (int j = 0; j < 8; j++) {
            int4 ra = ysrow[j];
            int4 rb = yorow[j];
            const __half2* ha = (const __half2*)&ra;
            const __half2* hb = (const __half2*)&rb;
#pragma unroll
            for (int k = 0; k < 4; k++) {
                int ch = j * 8 + k * 2;
                float v0 = __half2float(ha[k].x) + __half2float(hb[k].x) + s_yp[ch * 9 + cls];
                float v1 = __half2float(ha[k].y) + __half2float(hb[k].y) + s_yp[(ch + 1) * 9 + cls];
                s_val[ch * 256 + px]       = v0;
                s_val[(ch + 1) * 256 + px] = v1;
            }
        }
    }
    __syncthreads();

    for (int ch = 0; ch < 64; ch++) {
        float val = s_val[ch * 256 + px];
        float sm_ = val, sq = val * val;
#pragma unroll
        for (int off = 16; off > 0; off >>= 1) {
            sm_ += __shfl_xor_sync(0xffffffffu, sm_, off);
            sq  += __shfl_xor_sync(0xffffffffu, sq,  off);
        }
        if (lane == 0) { s_sum[ch * 8 + w] = sm_; s_ssq[ch * 8 + w] = sq; }
    }
    __syncthreads();
    if (tid < 64) {
        float S = 0.f, SS = 0.f;
#pragma unroll
        for (int k = 0; k < 8; k++) { S += s_sum[tid * 8 + k]; SS += s_ssq[tid * 8 + k]; }
        float m = S * (1.f / 256.f);
        float var = SS * (1.f / 256.f) - m * m;
        s_mean[tid] = m;
        s_scl[tid]  = rsqrtf(var + 1e-5f);
    }
    __syncthreads();

    u32 outw[32];
#pragma unroll
    for (int c2 = 0; c2 < 32; c2++) {
        int ch = c2 * 2;
        float f0 = (s_val[ch * 256 + px] - s_mean[ch]) * s_scl[ch];
        float f1 = (s_val[(ch + 1) * 256 + px] - s_mean[ch + 1]) * s_scl[ch + 1];
        f0 = (f0 >= 0.f) ? f0 : 0.1f * f0;
        f1 = (f1 >= 0.f) ? f1 : 0.1f * f1;
        __half2 hp(__float2half_rn(f0), __float2half_rn(f1));
        outw[c2] = *(u32*)&hp;
    }
    int4* dst = (int4*)(t1h + ((size_t)t * HW + px) * HID + hh * 64);
#pragma unroll
    for (int j = 0; j < 8; j++) dst[j] = ((int4*)outw)[j];
}

// ===========================================================================
// Deterministic segment SUM of t1 (fp16 [px][ch]) + counts.
// ===========================================================================
__global__ void __launch_bounds__(256) pool_t1(
    const __half* __restrict__ t1h, const int* __restrict__ edges,
    __half* __restrict__ T1sh, __half* __restrict__ T1oh, float* __restrict__ CNT)
{
    __shared__ int es[T_N], eo[T_N];
    __shared__ int listS[T_N], listO[T_N];
    __shared__ int cS, cO;

    const int o   = blockIdx.x;
    const int tid = threadIdx.x;

    for (int i = tid; i < T_N; i += 256) {
        es[i] = edges[2 * i];
        eo[i] = edges[2 * i + 1];
    }
    __syncthreads();
    if (tid == 0) { int c = 0; for (int t = 0; t < T_N; t++) if (es[t] == o) listS[c++] = t; cS = c; }
    if (tid == 32){ int c = 0; for (int t = 0; t < T_N; t++) if (eo[t] == o) listO[c++] = t; cO = c; }
    __syncthreads();
    const int cs = cS, co = cO;

    for (int cb = 0; cb < 4; cb++) {
        float accS[32], accO[32];
#pragma unroll
        for (int j = 0; j < 32; j++) { accS[j] = 0.f; accO[j] = 0.f; }
        for (int m = 0; m < cs; m++) {
            const int4* src = (const int4*)(t1h + ((size_t)listS[m] * HW + tid) * HID + cb * 32);
#pragma unroll
            for (int j = 0; j < 4; j++) {
                int4 r = src[j];
                const __half2* h = (const __half2*)&r;
#pragma unroll
                for (int k = 0; k < 4; k++) {
                    accS[j * 8 + k * 2]     += __half2float(h[k].x);
                    accS[j * 8 + k * 2 + 1] += __half2float(h[k].y);
                }
            }
        }
        for (int m = 0; m < co; m++) {
            const int4* src = (const int4*)(t1h + ((size_t)listO[m] * HW + tid) * HID + cb * 32);
#pragma unroll
            for (int j = 0; j < 4; j++) {
                int4 r = src[j];
                const __half2* h = (const __half2*)&r;
#pragma unroll
                for (int k = 0; k < 4; k++) {
                    accO[j * 8 + k * 2]     += __half2float(h[k].x);
                    accO[j * 8 + k * 2 + 1] += __half2float(h[k].y);
                }
            }
        }
        u32 ow[16];
#pragma unroll
        for (int j = 0; j < 16; j++) {
            __half2 hp(__float2half_rn(accS[j * 2]), __float2half_rn(accS[j * 2 + 1]));
            ow[j] = *(u32*)&hp;
        }
        int4* ds = (int4*)(T1sh + ((size_t)o * HW + tid) * HID + cb * 32);
#pragma unroll
        for (int j = 0; j < 4; j++) ds[j] = ((int4*)ow)[j];
#pragma unroll
        for (int j = 0; j < 16; j++) {
            __half2 hp(__float2half_rn(accO[j * 2]), __float2half_rn(accO[j * 2 + 1]));
            ow[j] = *(u32*)&hp;
        }
        int4* dv = (int4*)(T1oh + ((size_t)o * HW + tid) * HID + cb * 32);
#pragma unroll
        for (int j = 0; j < 4; j++) dv[j] = ((int4*)ow)[j];
    }
    if (tid == 0) { CNT[o] = (float)cs; CNT[O_N + o] = (float)co; }
}

// ===========================================================================
// tconv body: single-term fp16 implicit-GEMM conv, M-SPLIT (M=64, N=256).
// 256 thr / 8 warps; A double-buffered; 2 CTAs/SM.
// INH:  X is fp16 [n][px][CIN] (pure int4 staging);
//       else fp32 [n][ch][px] (load+cvt staging).
// OUTH: OUT is fp16 [n][px][128] (this CTA writes ch [mhalf*64,+64) via
//       smem transpose); else fp32 [n][ch][px].
// VARIANT: 2 inorm | 3 inorm add(fp32 out) | 5 pooled epi | 6 raw
// ===========================================================================
#define OFF_A0   0
#define OFF_A1   9216
#define OFF_XH   18432
#define OFF_SUM  55440            // 18432 + 257*144
#define OFF_SSQ  (55440 + 2048)
#define SMEM_SZ  (55440 + 4096)

template<int CIN, int KS, int VARIANT, bool INH, bool OUTH>
__device__ __forceinline__ void tconv_body(
    int n, int mhalf,
    const void* __restrict__ Xv,
    const void* __restrict__ X2v,
    const __half* __restrict__ WH,
    const float* __restrict__ BIAS,
    const float* __restrict__ CNT,
    void* __restrict__ OUTv)
{
    constexpr int KS2 = KS * KS;
    constexpr int NCHUNK = CIN / 64;
    extern __shared__ __align__(16) char smem[];
    const u32 sb = smem_u32(smem);

    const int tid  = threadIdx.x;
    const int lane = tid & 31;
    const int wid  = tid >> 5;
    const int wn   = wid;

    if (tid < 36)
        *(u32*)(smem + OFF_XH + 256 * 144 + tid * 4) = 0u;

    float acc[4][4][4];
#pragma unroll
    for (int a = 0; a < 4; a++)
#pragma unroll
        for (int b = 0; b < 4; b++)
#pragma unroll
            for (int c = 0; c < 4; c++) acc[a][b][c] = 0.f;

    const int nl    = (lane & 7) + ((lane >> 4) & 1) * 8;
    const int khalf = (lane >> 3) & 1;
    const int kha   = (lane >> 4) & 1;
    const u32 aOff  = (u32)((lane & 15) * 144 + kha * 16);
    const size_t wsub = (size_t)mhalf * 4608;

    {
        const int4* s = (const int4*)(WH + wsub);
        for (int i = tid; i < 576; i += 256) cpa16(sb + OFF_A0 + i * 16, s + i);
    }
    CP_COMMIT();
    int buf = 0;

    for (int chunk = 0; chunk < NCHUNK; chunk++) {
        __syncthreads();
        // ---- stage X chunk -> fp16 plane [px][64ci], 144B rows ----
        if (INH) {
            const __half* xb;
            if (VARIANT == 5) {
                xb = (chunk < 2)
                    ? (const __half*)Xv  + (size_t)n * HW * 128 + chunk * 64
                    : (const __half*)X2v + (size_t)n * HW * 128 + (chunk - 2) * 64;
            } else {
                xb = (const __half*)Xv + (size_t)n * HW * CIN + chunk * 64;
            }
            constexpr int RS = (VARIANT == 5) ? 128 : CIN;   // row stride in halfs
            for (int i = tid; i < 256 * 8; i += 256) {
                int p = i >> 3;
                int j = i & 7;
                int4 val = *(const int4*)(xb + (size_t)p * RS + j * 8);
                *(int4*)(smem + OFF_XH + p * 144 + j * 16) = val;
            }
        } else {
            const float* Xf = (const float*)Xv;
            for (int i = tid; i < 32 * 256; i += 256) {
                int cc = (i >> 8) * 2;
                int p  = i & 255;
                const float* s = Xf + ((size_t)n * CIN + chunk * 64 + cc) * HW + p;
                float v0 = s[0], v1 = s[HW];
                *(__half2*)(smem + OFF_XH + p * 144 + cc * 2) =
                    __half2(__float2half_rn(v0), __float2half_rn(v1));
            }
        }

        for (int tap = 0; tap < KS2; tap++) {
            CP_WAIT0();
            __syncthreads();

            {
                int nt = tap + 1, nc = chunk;
                if (nt == KS2) { nt = 0; nc = chunk + 1; }
                if (nc < NCHUNK) {
                    const int4* s = (const int4*)(WH + (size_t)(nt * NCHUNK + nc) * 9216 + wsub);
                    u32 d = sb + (buf ? OFF_A0 : OFF_A1);
                    for (int i = tid; i < 576; i += 256) cpa16(d + i * 16, s + i);
                    CP_COMMIT();
                }
            }

            const int dy = (KS == 3) ? (tap / 3 - 1) : 0;
            const int dx = (KS == 3) ? (tap % 3 - 1) : 0;
            u32 bBH[2];
#pragma unroll
            for (int nb = 0; nb < 2; nb++) {
                int p = wn * 32 + nb * 16 + nl;
                int y = p >> 4, x = p & 15;
                int ys_ = y + dy, xs = x + dx;
                u32 row = (((unsigned)ys_ < 16u) && ((unsigned)xs < 16u))
                              ? (u32)(ys_ * 16 + xs) : 256u;
                bBH[nb] = sb + OFF_XH + row * 144 + khalf * 16;
            }
            const u32 aB = sb + (buf ? OFF_A1 : OFF_A0) + aOff;

#pragma unroll
            for (int ks = 0; ks < 4; ks++) {
                const u32 kb = ks * 32;
                u32 bh[2][4];
                ldsm4(bh[0], bBH[0] + kb);
                ldsm4(bh[1], bBH[1] + kb);
                u32 a[4][4];
#pragma unroll
                for (int mt = 0; mt < 4; mt++) ldsm4(a[mt], aB + mt * 2304 + kb);
#pragma unroll
                for (int mt = 0; mt < 4; mt++)
#pragma unroll
                    for (int nf = 0; nf < 4; nf++)
                        mma16816(acc[mt][nf], a[mt], &bh[nf >> 1][(nf & 1) * 2]);
            }
            buf ^= 1;
        }
    }

    // ======================= epilogue =======================
    constexpr bool do_inorm = (VARIANT == 2 || VARIANT == 3);
    const int q    = lane >> 2;
    const int csub = lane & 3;

    float* s_sum = (float*)(smem + OFF_SUM);
    float* s_ssq = (float*)(smem + OFF_SSQ);

    float mean[4][2], scl[4][2], extra[4][2];
    float inv5 = 1.f;

    __syncthreads();

    if (do_inorm) {
#pragma unroll
        for (int mt = 0; mt < 4; mt++)
#pragma unroll
            for (int h = 0; h < 2; h++) {
                float sm = 0.f, sq = 0.f;
#pragma unroll
                for (int nf = 0; nf < 4; nf++) {
                    float v = acc[mt][nf][2 * h], w = acc[mt][nf][2 * h + 1];
                    sm += v + w;
                    sq += v * v + w * w;
                }
                sm += __shfl_xor_sync(0xffffffffu, sm, 1);
                sq += __shfl_xor_sync(0xffffffffu, sq, 1);
                sm += __shfl_xor_sync(0xffffffffu, sm, 2);
                sq += __shfl_xor_sync(0xffffffffu, sq, 2);
                if (csub == 0) {
                    int r = mt * 16 + q + h * 8;
                    s_sum[r * 8 + wn] = sm;
                    s_ssq[r * 8 + wn] = sq;
                }
            }
        __syncthreads();
#pragma unroll
        for (int mt = 0; mt < 4; mt++)
#pragma unroll
            for (int h = 0; h < 2; h++) {
                int r = mt * 16 + q + h * 8;
                float S = 0.f, SS = 0.f;
#pragma unroll
                for (int w = 0; w < 8; w++) { S += s_sum[r * 8 + w]; SS += s_ssq[r * 8 + w]; }
                float m = S * (1.f / 256.f);
                float var = SS * (1.f / 256.f) - m * m;
                mean[mt][h] = m;
                scl[mt][h]  = rsqrtf(var + 1e-5f);
            }
    } else if (VARIANT == 5) {
        float cs = CNT[n], cf = CNT[O_N + n];
        inv5 = 1.f / fmaxf(cs + cf, 1.f);
#pragma unroll
        for (int mt = 0; mt < 4; mt++)
#pragma unroll
            for (int h = 0; h < 2; h++) {
                int gco = mhalf * 64 + mt * 16 + q + h * 8;
                extra[mt][h] = cs * BIAS[gco] + cf * BIAS[256 + gco];
            }
    }

    if (OUTH) {
        // write fp16 into smem plane [px][72 halfs], then copy rows out
        __half* sph = (__half*)(smem + OFF_XH);
        if (do_inorm) __syncthreads();   // s_sum path already synced; keep plane safe
#pragma unroll
        for (int mt = 0; mt < 4; mt++)
#pragma unroll
            for (int h = 0; h < 2; h++) {
                int ch = mt * 16 + q + h * 8;
#pragma unroll
                for (int nf = 0; nf < 4; nf++) {
                    int c = wn * 32 + nf * 8 + csub * 2;
                    float v0 = acc[mt][nf][2 * h];
                    float v1 = acc[mt][nf][2 * h + 1];
                    if (do_inorm) {
                        v0 = (v0 - mean[mt][h]) * scl[mt][h];
                        v1 = (v1 - mean[mt][h]) * scl[mt][h];
                        v0 = (v0 >= 0.f) ? v0 : 0.1f * v0;
                        v1 = (v1 >= 0.f) ? v1 : 0.1f * v1;
                    } else if (VARIANT == 5) {
                        v0 = (v0 + extra[mt][h]) * inv5;
                        v1 = (v1 + extra[mt][h]) * inv5;
                    }
                    sph[c * 72 + ch]       = __float2half_rn(v0);
                    sph[(c + 1) * 72 + ch] = __float2half_rn(v1);
                }
            }
        __syncthreads();
        __half* dsth = (__half*)OUTv + ((size_t)n * HW + tid) * 128 + mhalf * 64;
        const int4* srow = (const int4*)(sph + tid * 72);
        int4* drow = (int4*)dsth;
#pragma unroll
        for (int j = 0; j < 8; j++) drow[j] = srow[j];
    } else {
        float* dst = (float*)OUTv + (size_t)n * HID * HW;
#pragma unroll
        for (int mt = 0; mt < 4; mt++)
#pragma unroll
            for (int h = 0; h < 2; h++) {
                int gco = mhalf * 64 + mt * 16 + q + h * 8;
                float* rowp = dst + (size_t)gco * HW;
#pragma unroll
                for (int nf = 0; nf < 4; nf++) {
                    int c = wn * 32 + nf * 8 + csub * 2;
                    float v0 = acc[mt][nf][2 * h];
                    float v1 = acc[mt][nf][2 * h + 1];
                    if (do_inorm) {
                        v0 = (v0 - mean[mt][h]) * scl[mt][h];
                        v1 = (v1 - mean[mt][h]) * scl[mt][h];
                        v0 = (v0 >= 0.f) ? v0 : 0.1f * v0;
                        v1 = (v1 >= 0.f) ? v1 : 0.1f * v1;
                    }
                    float2* p2 = (float2*)(rowp + c);
                    if (VARIANT == 3) {
                        float2 old = *p2;
                        *p2 = make_float2(old.x + v0, old.y + v1);
                    } else {
                        *p2 = make_float2(v0, v1);
                    }
                }
            }
    }
}

// Generic wrapper: grid (n, 2) -> (image, co-half)
template<int CIN, int KS, int VARIANT, bool INH, bool OUTH>
__global__ void __launch_bounds__(256, 2) tconv(
    const void* __restrict__ X,
    const void* __restrict__ X2,
    const __half* __restrict__ WH,
    const float* __restrict__ BIAS,
    const float* __restrict__ CNT,
    void* __restrict__ OUT)
{
    tconv_body<CIN, KS, VARIANT, INH, OUTH>(blockIdx.x, blockIdx.y, X, X2, WH, BIAS, CNT, OUT);
}

// ys/yo fused: grid (512, 4): y&1 = co-half, y>>1 = s/o select.
__global__ void __launch_bounds__(256, 2) ysyo_kernel(
    const float* __restrict__ obj_maps,
    const __half* __restrict__ was, const __half* __restrict__ wao,
    __half* __restrict__ ys, __half* __restrict__ yo)
{
    const __half* W = ((blockIdx.y >> 1) == 0) ? was : wao;
    __half* OUT     = ((blockIdx.y >> 1) == 0) ? ys  : yo;
    tconv_body<64, 3, 6, false, true>(blockIdx.x, blockIdx.y & 1, obj_maps, nullptr, W,
                                      nullptr, nullptr, OUT);
}

// ===========================================================================
// Launch
// ===========================================================================
extern "C" void kernel_launch(void* const* d_in, const int* in_sizes, int n_in,
                              void* d_out, int out_size)
{
    const float* obj_maps = (const float*)d_in[0];
    const float* pred     = (const float*)d_in[1];
    const int*   edges    = (const int*)  d_in[2];
    const float* w1a = (const float*)d_in[4];
    const float* w1b = (const float*)d_in[6];
    const float* b1b = (const float*)d_in[7];
    const float* w2a = (const float*)d_in[8];
    const float* w2b = (const float*)d_in[10];
    const float* woa = (const float*)d_in[12];
    const float* wob = (const float*)d_in[14];

    float* out_obj = (float*)d_out;
    float* out_p   = out_obj + (size_t)O_N * HID * HW;

    __half *t1, *ys, *yo, *T1s, *T1o, *pooled, *u, *v;
    float *yp, *wc, *cnt;
    cudaGetSymbolAddress((void**)&t1,     g_t1);
    cudaGetSymbolAddress((void**)&ys,     g_ys);
    cudaGetSymbolAddress((void**)&yo,     g_yo);
    cudaGetSymbolAddress((void**)&T1s,    g_T1s);
    cudaGetSymbolAddress((void**)&T1o,    g_T1o);
    cudaGetSymbolAddress((void**)&pooled, g_pooled);
    cudaGetSymbolAddress((void**)&u,      g_u);
    cudaGetSymbolAddress((void**)&v,      g_v);
    cudaGetSymbolAddress((void**)&yp,     g_yp);
    cudaGetSymbolAddress((void**)&wc,     g_wc);
    cudaGetSymbolAddress((void**)&cnt,    g_cnt);

    __half *was, *wao, *w1bp, *w1bso, *w2ah, *w2bh, *woah, *wobh;
    cudaGetSymbolAddress((void**)&was,   g_was);
    cudaGetSymbolAddress((void**)&wao,   g_wao);
    cudaGetSymbolAddress((void**)&w1bp,  g_w1bp);
    cudaGetSymbolAddress((void**)&w1bso, g_w1bso);
    cudaGetSymbolAddress((void**)&w2ah,  g_w2a);
    cudaGetSymbolAddress((void**)&w2bh,  g_w2b);
    cudaGetSymbolAddress((void**)&woah,  g_woa);
    cudaGetSymbolAddress((void**)&wobh,  g_wob);

    cudaFuncSetAttribute(ysyo_kernel, cudaFuncAttributeMaxDynamicSharedMemorySize, SMEM_SZ);
    cudaFuncSetAttribute(tconv<64,3,2,false,true>,  cudaFuncAttributeMaxDynamicSharedMemorySize, SMEM_SZ);
    cudaFuncSetAttribute(tconv<128,1,2,true,false>, cudaFuncAttributeMaxDynamicSharedMemorySize, SMEM_SZ);
    cudaFuncSetAttribute(tconv<128,3,2,true,false>, cudaFuncAttributeMaxDynamicSharedMemorySize, SMEM_SZ);
    cudaFuncSetAttribute(tconv<256,3,5,true,true>,  cudaFuncAttributeMaxDynamicSharedMemorySize, SMEM_SZ);
    cudaFuncSetAttribute(tconv<128,3,2,true,true>,  cudaFuncAttributeMaxDynamicSharedMemorySize, SMEM_SZ);
    cudaFuncSetAttribute(tconv<128,1,3,true,false>, cudaFuncAttributeMaxDynamicSharedMemorySize, SMEM_SZ);
    cudaFuncSetAttribute(combine_h, cudaFuncAttributeMaxDynamicSharedMemorySize, CBH_SMEM);

    cudaStream_t s1 = g_res.s1, s2 = g_res.s2;
    cudaEvent_t  eP = g_res.eP, eW = g_res.eW, eC = g_res.eC,
                 e1 = g_res.e1, e2 = g_res.e2;

    // ---- mega weight prep ----
    PrepTable tab;
    tab.d[0] = { w1a, was,     0,   0, 192, 9, 1, 0, 1 };
    tab.d[1] = { w1a, wao,     0, 128, 192, 9, 1, 0, 1 };
    tab.d[2] = { w1b, w1bp,  128,   0, 128, 9, 2, 0, 2 };
    tab.d[3] = { w1b, w1bso,   0,   0, 128, 9, 2, 0, 4 };
    tab.d[4] = { w1b, w1bso, 256,   0, 128, 9, 2, 2, 4 };
    tab.d[5] = { w2a, w2ah,    0,   0, 128, 9, 2, 0, 2 };
    tab.d[6] = { w2b, w2bh,    0,   0, 128, 1, 2, 0, 2 };
    tab.d[7] = { woa, woah,    0,   0,  64, 9, 1, 0, 1 };
    tab.d[8] = { wob, wobh,    0,   0, 128, 1, 2, 0, 2 };
    megaprep<<<dim3(64, 9), 256>>>(tab);
    cudaEventRecord(eP, 0);

    // Side branch s2: wc + yp under the ysyo conv
    cudaStreamWaitEvent(s2, eP, 0);
    wc_kernel<<<(9*128*64 + 255) / 256, 256, 0, s2>>>(w1a, wc);
    yp_kernel<<<T_N, 256, 0, s2>>>(pred, wc, yp);
    cudaEventRecord(eW, s2);

    // Side branch s1: v = block(obj_maps, woa) [fp16 out]; out_obj = block(v, wob) (WRITE fp32)
    cudaStreamWaitEvent(s1, eP, 0);
    tconv<64,3,2,false,true><<<dim3(O_N,2), 256, SMEM_SZ, s1>>>(
        obj_maps, nullptr, woah, nullptr, nullptr, v);
    tconv<128,1,2,true,false><<<dim3(O_N,2), 256, SMEM_SZ, s1>>>(
        v, nullptr, wobh, nullptr, nullptr, out_obj);
    cudaEventRecord(e1, s1);

    // Main: ys|yo fused (fp16 out), then combine (fp16 in/out)
    ysyo_kernel<<<dim3(O_N, 4), 256, SMEM_SZ>>>(obj_maps, was, wao, ys, yo);
    cudaStreamWaitEvent(0, eW, 0);
    combine_h<<<dim3(T_N, 2), 256, CBH_SMEM>>>(ys, yo, yp, edges, t1);
    cudaEventRecord(eC, 0);

    // Side branch s2: new_p conv -> out_p (fp32)
    cudaStreamWaitEvent(s2, eC, 0);
    tconv<128,3,2,true,false><<<dim3(T_N,2), 256, SMEM_SZ, s2>>>(
        t1, nullptr, w1bp, nullptr, nullptr, out_p);
    cudaEventRecord(e2, s2);

    // Main: pool -> pooled conv (fp16 out) -> u (fp16 out) -> out_obj += w2b
    pool_t1<<<O_N, 256>>>(t1, edges, T1s, T1o, cnt);
    tconv<256,3,5,true,true><<<dim3(O_N,2), 256, SMEM_SZ>>>(
        T1s, T1o, w1bso, b1b, cnt, pooled);
    tconv<128,3,2,true,true><<<dim3(O_N,2), 256, SMEM_SZ>>>(
        pooled, nullptr, w2ah, nullptr, nullptr, u);
    cudaStreamWaitEvent(0, e1, 0);
    tconv<128,1,3,true,false><<<dim3(O_N,2), 256, SMEM_SZ>>>(
        u, nullptr, w2bh, nullptr, nullptr, out_obj);
    cudaStreamWaitEvent(0, e2, 0);
}

// round 16
// speedup vs baseline: 1.4296x; 1.4296x over previous
#include <cuda_runtime.h>
#include <cuda_fp16.h>
#include <cstdint>

typedef unsigned long long u64;
typedef uint32_t u32;

// Problem constants
#define O_N   512
#define T_N   1024
#define HW    256     // 16x16
#define DIN   64
#define DP    64
#define HID   128
#define DOUT  128

// ===========================================================================
// Side streams/events: created ONCE at program load (static initializer).
// ===========================================================================
struct SideRes {
    cudaStream_t s1, s2;
    cudaEvent_t  eP, eW, eC, e1, e2;
    SideRes() {
        cudaStreamCreateWithFlags(&s1, cudaStreamNonBlocking);
        cudaStreamCreateWithFlags(&s2, cudaStreamNonBlocking);
        cudaEventCreateWithFlags(&eP, cudaEventDisableTiming);
        cudaEventCreateWithFlags(&eW, cudaEventDisableTiming);
        cudaEventCreateWithFlags(&eC, cudaEventDisableTiming);
        cudaEventCreateWithFlags(&e1, cudaEventDisableTiming);
        cudaEventCreateWithFlags(&e2, cudaEventDisableTiming);
    }
};
static SideRes g_res;

// ===========================================================================
// mma.sync / ldmatrix / cp.async helpers
// ===========================================================================
__device__ __forceinline__ u32 smem_u32(const void* p) {
    u32 a;
    asm("{ .reg .u64 t; cvta.to.shared.u64 t, %1; cvt.u32.u64 %0, t; }" : "=r"(a) : "l"(p));
    return a;
}
__device__ __forceinline__ void ldsm4(u32* r, u32 addr) {
    asm volatile("ldmatrix.sync.aligned.m8n8.x4.shared.b16 {%0,%1,%2,%3}, [%4];"
                 : "=r"(r[0]), "=r"(r[1]), "=r"(r[2]), "=r"(r[3]) : "r"(addr));
}
__device__ __forceinline__ void mma16816(float* d, const u32* a, const u32* b) {
    asm volatile(
        "mma.sync.aligned.m16n8k16.row.col.f32.f16.f16.f32 "
        "{%0,%1,%2,%3}, {%4,%5,%6,%7}, {%8,%9}, {%0,%1,%2,%3};"
        : "+f"(d[0]), "+f"(d[1]), "+f"(d[2]), "+f"(d[3])
        : "r"(a[0]), "r"(a[1]), "r"(a[2]), "r"(a[3]), "r"(b[0]), "r"(b[1]));
}
__device__ __forceinline__ void cpa16(u32 dst, const void* src) {
    asm volatile("cp.async.cg.shared.global [%0], [%1], 16;" :: "r"(dst), "l"(src));
}
#define CP_COMMIT() asm volatile("cp.async.commit_group;" ::: "memory")
#define CP_WAIT0()  asm volatile("cp.async.wait_group 0;" ::: "memory")

// ===========================================================================
// Scratch buffers (fp32, [n][ch][px] layout)
// ===========================================================================
__device__ float g_t1 [(size_t)T_N * HID * HW];
__device__ float g_ys [(size_t)O_N * HID * HW];
__device__ float g_yo [(size_t)O_N * HID * HW];
__device__ float g_T1s[(size_t)O_N * HID * HW];
__device__ float g_T1o[(size_t)O_N * HID * HW];
__device__ float g_pooled[(size_t)O_N * HID * HW];
__device__ float g_u  [(size_t)O_N * HID * HW];
__device__ float g_v  [(size_t)O_N * HID * HW];
__device__ float g_yp [(size_t)T_N * HID * 9];
__device__ float g_wc [9 * HID * 64];
__device__ float g_cnt[2 * O_N];

// fp16 weights, padded tile layout (tile = tap*NCHUNK+chunk; [co][72 halfs])
__device__ __align__(16) __half g_was  [ 82944];
__device__ __align__(16) __half g_wao  [ 82944];
__device__ __align__(16) __half g_w1bp [165888];
__device__ __align__(16) __half g_w1bso[331776];
__device__ __align__(16) __half g_w2a  [165888];
__device__ __align__(16) __half g_w2b  [ 18432];
__device__ __align__(16) __half g_woa  [ 82944];
__device__ __align__(16) __half g_wob  [ 18432];

// ===========================================================================
// Mega weight prep
// ===========================================================================
struct PrepDesc {
    const float* W;
    __half* H;
    int co_off, ci_off, cin, ks2, nch, dst_ch0, dst_nch;
};
struct PrepTable { PrepDesc d[9]; };

__global__ void __launch_bounds__(256) megaprep(PrepTable tab)
{
    PrepDesc d = tab.d[blockIdx.y];
    const int per_co = d.ks2 * d.nch * 72;
    const int total  = 128 * per_co;
    for (int idx = blockIdx.x * blockDim.x + threadIdx.x; idx < total;
         idx += gridDim.x * blockDim.x) {
        int co   = idx / per_co;
        int rem  = idx % per_co;
        int t    = rem / (d.nch * 72);
        int rem2 = rem % (d.nch * 72);
        int ch   = rem2 / 72;
        int c72  = rem2 % 72;
        float v = 0.f;
        if (c72 < 64)
            v = d.W[((size_t)(co + d.co_off) * d.cin + d.ci_off + ch * 64 + c72) * d.ks2 + t];
        int tile = t * d.dst_nch + d.dst_ch0 + ch;
        d.H[(size_t)tile * 9216 + (size_t)co * 72 + c72] = __float2half_rn(v);
    }
}

// Wc[cls][co][ci]
__global__ void wc_kernel(const float* __restrict__ w1a, float* __restrict__ Wc) {
    int idx = blockIdx.x * blockDim.x + threadIdx.x;
    if (idx >= 9 * 128 * 64) return;
    int cls = idx / (128 * 64);
    int co  = (idx / 64) % 128;
    int ci  = idx % 64;
    int cy = cls / 3, cx = cls % 3;
    float sum = 0.f;
    for (int ky = 0; ky < 3; ky++) {
        if ((cy == 0 && ky == 0) || (cy == 2 && ky == 2)) continue;
        for (int kx = 0; kx < 3; kx++) {
            if ((cx == 0 && kx == 0) || (cx == 2 && kx == 2)) continue;
            sum += w1a[((size_t)co * 192 + 64 + ci) * 9 + ky * 3 + kx];
        }
    }
    Wc[idx] = sum;
}

// yp[t][co*9+cls]
__global__ void __launch_bounds__(256) yp_kernel(
    const float* __restrict__ pred, const float* __restrict__ Wc,
    float* __restrict__ yp)
{
    __shared__ float sp[64];
    int t = blockIdx.x;
    int tid = threadIdx.x;
    if (tid < 64) sp[tid] = pred[(size_t)t * DP + tid];
    __syncthreads();
    for (int i = tid; i < 128 * 9; i += 256) {
        int co = i / 9, cls = i % 9;
        const float* wc = Wc + ((size_t)cls * 128 + co) * 64;
        float sum = 0.f;
#pragma unroll 16
        for (int ci = 0; ci < 64; ci++) sum += sp[ci] * wc[ci];
        yp[(size_t)t * 1152 + i] = sum;
    }
}

// ===========================================================================
// Combine v2 (channel-split, smem-cached): t1 = lrelu(inorm(ys[s]+yp+yo[o]))
// ===========================================================================
#define CB2_VAL   0
#define CB2_YP    16384
#define CB2_SUM   (16384 + 576)
#define CB2_SSQ   (16384 + 576 + 512)
#define CB2_MEAN  (16384 + 576 + 1024)
#define CB2_SCL   (16384 + 576 + 1024 + 64)
#define CB2_SMEM  ((16384 + 576 + 1024 + 128) * 4)

__global__ void __launch_bounds__(256) combine2(
    const float* __restrict__ ys, const float* __restrict__ yo,
    const float* __restrict__ yp, const int* __restrict__ edges,
    float* __restrict__ t1)
{
    extern __shared__ float sm[];
    float* s_val  = sm + CB2_VAL;
    float* s_yp   = sm + CB2_YP;
    float* s_sum  = sm + CB2_SUM;
    float* s_ssq  = sm + CB2_SSQ;
    float* s_mean = sm + CB2_MEAN;
    float* s_scl  = sm + CB2_SCL;

    const int t   = blockIdx.x;
    const int hh  = blockIdx.y;
    const int tid = threadIdx.x;
    const int lane = tid & 31;
    const int w    = tid >> 5;
    const int s = edges[2 * t], o = edges[2 * t + 1];

    for (int i = tid; i < 576; i += 256)
        s_yp[i] = yp[(size_t)t * 1152 + hh * 576 + i];
    __syncthreads();

    const int px = tid;
    const int y = px >> 4, x = px & 15;
    const int cy = (y == 0) ? 0 : ((y == 15) ? 2 : 1);
    const int cx = (x == 0) ? 0 : ((x == 15) ? 2 : 1);
    const int cls = cy * 3 + cx;
    const float* ysb = ys + ((size_t)s * HID + hh * 64) * HW + px;
    const float* yob = yo + ((size_t)o * HID + hh * 64) * HW + px;

    for (int ch = 0; ch < 64; ch++) {
        float val = ysb[ch * HW] + yob[ch * HW] + s_yp[ch * 9 + cls];
        s_val[ch * 256 + px] = val;
        float sm_ = val, sq = val * val;
#pragma unroll
        for (int off = 16; off > 0; off >>= 1) {
            sm_ += __shfl_xor_sync(0xffffffffu, sm_, off);
            sq  += __shfl_xor_sync(0xffffffffu, sq,  off);
        }
        if (lane == 0) { s_sum[ch * 8 + w] = sm_; s_ssq[ch * 8 + w] = sq; }
    }
    __syncthreads();
    if (tid < 64) {
        float S = 0.f, SS = 0.f;
#pragma unroll
        for (int k = 0; k < 8; k++) { S += s_sum[tid * 8 + k]; SS += s_ssq[tid * 8 + k]; }
        float m = S * (1.f / 256.f);
        float var = SS * (1.f / 256.f) - m * m;
        s_mean[tid] = m;
        s_scl[tid]  = rsqrtf(var + 1e-5f);
    }
    __syncthreads();
    float* dst = t1 + ((size_t)t * HID + hh * 64) * HW + px;
    for (int ch = 0; ch < 64; ch++) {
        float vv = (s_val[ch * 256 + px] - s_mean[ch]) * s_scl[ch];
        dst[ch * HW] = (vv >= 0.f) ? vv : 0.1f * vv;
    }
}

// ===========================================================================
// Deterministic segment SUM of t1 over s-edges and o-edges, plus counts.
// ===========================================================================
__global__ void __launch_bounds__(256) pool_t1(
    const float* __restrict__ t1, const int* __restrict__ edges,
    float* __restrict__ T1s, float* __restrict__ T1o, float* __restrict__ CNT)
{
    __shared__ int es[T_N], eo[T_N];
    __shared__ int listS[T_N], listO[T_N];
    __shared__ int cS, cO;

    const int o   = blockIdx.x;
    const int tid = threadIdx.x;

    for (int i = tid; i < T_N; i += 256) {
        es[i] = edges[2 * i];
        eo[i] = edges[2 * i + 1];
    }
    __syncthreads();
    if (tid == 0) { int c = 0; for (int t = 0; t < T_N; t++) if (es[t] == o) listS[c++] = t; cS = c; }
    if (tid == 32){ int c = 0; for (int t = 0; t < T_N; t++) if (eo[t] == o) listO[c++] = t; cO = c; }
    __syncthreads();
    const int cs = cS, co = cO;

    for (int cb = 0; cb < 4; cb++) {
        float accS[32], accO[32];
#pragma unroll
        for (int j = 0; j < 32; j++) { accS[j] = 0.f; accO[j] = 0.f; }
        for (int m = 0; m < cs; m++) {
            const float* src = t1 + ((size_t)listS[m] * HID + cb * 32) * HW + tid;
#pragma unroll
            for (int j = 0; j < 32; j++) accS[j] += src[(size_t)j * HW];
        }
        for (int m = 0; m < co; m++) {
            const float* src = t1 + ((size_t)listO[m] * HID + cb * 32) * HW + tid;
#pragma unroll
            for (int j = 0; j < 32; j++) accO[j] += src[(size_t)j * HW];
        }
#pragma unroll
        for (int j = 0; j < 32; j++) {
            T1s[((size_t)o * HID + cb * 32 + j) * HW + tid] = accS[j];
            T1o[((size_t)o * HID + cb * 32 + j) * HW + tid] = accO[j];
        }
    }
    if (tid == 0) { CNT[o] = (float)cs; CNT[O_N + o] = (float)co; }
}

// ===========================================================================
// tconv body: single-term fp16 implicit-GEMM conv, M-SPLIT (M=64, N=256).
// A tiles prefetched in GROUPS of GS taps (GS=3 for 3x3), double-buffered:
// 4 sync points per chunk instead of 10; each tensor run = GS taps.
// Per-tap A half-tile = 64 co x 144B = 9216B = 576 int4 (R15 bug: was 288).
// 256 thr / 8 warps; 2 CTAs/SM (96.4KB smem each).
// VARIANT: 2 inorm->OUT | 3 inorm add->OUT | 5 dual-input pooled conv | 6 raw
// ===========================================================================
#define OFF_A0   0                        // GSmax(3) * 9216 = 27648
#define OFF_A1   27648
#define OFF_XH   55296
#define OFF_SUM  92304                    // 55296 + 257*144
#define OFF_SSQ  (92304 + 2048)
#define SMEM_SZ  (92304 + 4096)

template<int CIN, int KS, int VARIANT>
__device__ __forceinline__ void tconv_body(
    int n, int mhalf,
    const float* __restrict__ X,
    const float* __restrict__ X2,
    const __half* __restrict__ WH,
    const float* __restrict__ BIAS,
    const float* __restrict__ CNT,
    float* __restrict__ OUT)
{
    constexpr int KS2 = KS * KS;
    constexpr int NCHUNK = CIN / 64;
    constexpr int GS = (KS == 3) ? 3 : 1;      // taps per group
    constexpr int NG = KS2 / GS;               // groups per chunk
    extern __shared__ __align__(16) char smem[];
    const u32 sb = smem_u32(smem);

    const int tid  = threadIdx.x;
    const int lane = tid & 31;
    const int wid  = tid >> 5;
    const int wn   = wid;                 // 0..7 -> N 32-slice

    // zero row (pixel index 256) for OOB taps
    if (tid < 36)
        *(u32*)(smem + OFF_XH + 256 * 144 + tid * 4) = 0u;

    float acc[4][4][4];
#pragma unroll
    for (int a = 0; a < 4; a++)
#pragma unroll
        for (int b = 0; b < 4; b++)
#pragma unroll
            for (int c = 0; c < 4; c++) acc[a][b][c] = 0.f;

    const int nl    = (lane & 7) + ((lane >> 4) & 1) * 8;
    const int khalf = (lane >> 3) & 1;
    const int kha   = (lane >> 4) & 1;
    const u32 aOff  = (u32)((lane & 15) * 144 + kha * 16);
    const size_t wsub = (size_t)mhalf * 4608;   // co-half offset within a tile (halfs)

    for (int chunk = 0; chunk < NCHUNK; chunk++) {
        __syncthreads();   // prev chunk compute done (buffers + X plane reusable)

        // ---- prefetch group 0 (GS tap half-tiles, 576 int4 each) ----
        for (int i = tid; i < GS * 576; i += 256) {
            int k = i / 576;
            int j = i - k * 576;
            const int4* s = (const int4*)(WH + (size_t)(k * NCHUNK + chunk) * 9216 + wsub) + j;
            cpa16(sb + OFF_A0 + k * 9216 + j * 16, s);
        }
        CP_COMMIT();

        // ---- stage X chunk -> fp16 plane [px][64ci], 144B rows ----
        for (int i = tid; i < 32 * 256; i += 256) {
            int cc = (i >> 8) * 2;
            int p  = i & 255;
            const float* s;
            if (VARIANT == 5) {
                s = (chunk < 2)
                        ? X  + ((size_t)n * 128 + chunk * 64 + cc) * HW + p
                        : X2 + ((size_t)n * 128 + (chunk - 2) * 64 + cc) * HW + p;
            } else {
                s = X + ((size_t)n * CIN + chunk * 64 + cc) * HW + p;
            }
            float v0 = s[0], v1 = s[HW];
            *(__half2*)(smem + OFF_XH + p * 144 + cc * 2) =
                __half2(__float2half_rn(v0), __float2half_rn(v1));
        }

        CP_WAIT0();
        __syncthreads();   // group-0 A + X plane ready

        int buf = 0;
        for (int g = 0; g < NG; g++) {
            // prefetch next group into the other buffer
            if (g + 1 < NG) {
                u32 d = sb + (buf ? OFF_A0 : OFF_A1);
                for (int i = tid; i < GS * 576; i += 256) {
                    int k = i / 576;
                    int j = i - k * 576;
                    int tap = (g + 1) * GS + k;
                    const int4* s = (const int4*)(WH + (size_t)(tap * NCHUNK + chunk) * 9216 + wsub) + j;
                    cpa16(d + k * 9216 + j * 16, s);
                }
                CP_COMMIT();
            }

            const u32 abase = sb + (buf ? OFF_A1 : OFF_A0);
            // ---- compute GS taps back-to-back, no barriers ----
#pragma unroll
            for (int k = 0; k < GS; k++) {
                const int tap = g * GS + k;
                const int dy = (KS == 3) ? (tap / 3 - 1) : 0;
                const int dx = (KS == 3) ? (tap % 3 - 1) : 0;
                u32 bBH[2];
#pragma unroll
                for (int nb = 0; nb < 2; nb++) {
                    int p = wn * 32 + nb * 16 + nl;
                    int y = p >> 4, x = p & 15;
                    int ys_ = y + dy, xs = x + dx;
                    u32 row = (((unsigned)ys_ < 16u) && ((unsigned)xs < 16u))
                                  ? (u32)(ys_ * 16 + xs) : 256u;
                    bBH[nb] = sb + OFF_XH + row * 144 + khalf * 16;
                }
                const u32 aB = abase + k * 9216 + aOff;

#pragma unroll
                for (int ks = 0; ks < 4; ks++) {
                    const u32 kb = ks * 32;
                    u32 bh[2][4];
                    ldsm4(bh[0], bBH[0] + kb);
                    ldsm4(bh[1], bBH[1] + kb);
                    u32 a[4][4];
#pragma unroll
                    for (int mt = 0; mt < 4; mt++) ldsm4(a[mt], aB + mt * 2304 + kb);
#pragma unroll
                    for (int mt = 0; mt < 4; mt++)
#pragma unroll
                        for (int nf = 0; nf < 4; nf++)
                            mma16816(acc[mt][nf], a[mt], &bh[nf >> 1][(nf & 1) * 2]);
                }
            }

            if (g + 1 < NG) {
                CP_WAIT0();
                __syncthreads();
            }
            buf ^= 1;
        }
    }

    // ======================= epilogue =======================
    constexpr bool do_inorm = (VARIANT == 2 || VARIANT == 3);
    const int q    = lane >> 2;
    const int csub = lane & 3;

    float* s_sum = (float*)(smem + OFF_SUM);   // [64][8]
    float* s_ssq = (float*)(smem + OFF_SSQ);

    float mean[4][2], scl[4][2], extra[4][2];
    float inv5 = 1.f;

    __syncthreads();

    if (do_inorm) {
#pragma unroll
        for (int mt = 0; mt < 4; mt++)
#pragma unroll
            for (int h = 0; h < 2; h++) {
                float sm = 0.f, sq = 0.f;
#pragma unroll
                for (int nf = 0; nf < 4; nf++) {
                    float v = acc[mt][nf][2 * h], w = acc[mt][nf][2 * h + 1];
                    sm += v + w;
                    sq += v * v + w * w;
                }
                sm += __shfl_xor_sync(0xffffffffu, sm, 1);
                sq += __shfl_xor_sync(0xffffffffu, sq, 1);
                sm += __shfl_xor_sync(0xffffffffu, sm, 2);
                sq += __shfl_xor_sync(0xffffffffu, sq, 2);
                if (csub == 0) {
                    int r = mt * 16 + q + h * 8;
                    s_sum[r * 8 + wn] = sm;
                    s_ssq[r * 8 + wn] = sq;
                }
            }
        __syncthreads();
#pragma unroll
        for (int mt = 0; mt < 4; mt++)
#pragma unroll
            for (int h = 0; h < 2; h++) {
                int r = mt * 16 + q + h * 8;
                float S = 0.f, SS = 0.f;
#pragma unroll
                for (int w = 0; w < 8; w++) { S += s_sum[r * 8 + w]; SS += s_ssq[r * 8 + w]; }
                float m = S * (1.f / 256.f);
                float var = SS * (1.f / 256.f) - m * m;
                mean[mt][h] = m;
                scl[mt][h]  = rsqrtf(var + 1e-5f);
            }
    } else if (VARIANT == 5) {
        float cs = CNT[n], cf = CNT[O_N + n];
        inv5 = 1.f / fmaxf(cs + cf, 1.f);
#pragma unroll
        for (int mt = 0; mt < 4; mt++)
#pragma unroll
            for (int h = 0; h < 2; h++) {
                int gco = mhalf * 64 + mt * 16 + q + h * 8;
                extra[mt][h] = cs * BIAS[gco] + cf * BIAS[256 + gco];
            }
    }

    float* dst = OUT + (size_t)n * HID * HW;

#pragma unroll
    for (int mt = 0; mt < 4; mt++)
#pragma unroll
        for (int h = 0; h < 2; h++) {
            int gco = mhalf * 64 + mt * 16 + q + h * 8;
            float* rowp = dst + (size_t)gco * HW;
#pragma unroll
            for (int nf = 0; nf < 4; nf++) {
                int c = wn * 32 + nf * 8 + csub * 2;
                float v0 = acc[mt][nf][2 * h];
                float v1 = acc[mt][nf][2 * h + 1];
                if (do_inorm) {
                    v0 = (v0 - mean[mt][h]) * scl[mt][h];
                    v1 = (v1 - mean[mt][h]) * scl[mt][h];
                    v0 = (v0 >= 0.f) ? v0 : 0.1f * v0;
                    v1 = (v1 >= 0.f) ? v1 : 0.1f * v1;
                } else if (VARIANT == 5) {
                    v0 = (v0 + extra[mt][h]) * inv5;
                    v1 = (v1 + extra[mt][h]) * inv5;
                }
                float2* p2 = (float2*)(rowp + c);
                if (VARIANT == 3) {
                    float2 old = *p2;
                    *p2 = make_float2(old.x + v0, old.y + v1);
                } else {
                    *p2 = make_float2(v0, v1);
                }
            }
        }
}

// Generic wrapper: grid (n, 2) -> (image, co-half)
template<int CIN, int KS, int VARIANT>
__global__ void __launch_bounds__(256, 2) tconv(
    const float* __restrict__ X,
    const float* __restrict__ X2,
    const __half* __restrict__ WH,
    const float* __restrict__ BIAS,
    const float* __restrict__ CNT,
    float* __restrict__ OUT)
{
    tconv_body<CIN, KS, VARIANT>(blockIdx.x, blockIdx.y, X, X2, WH, BIAS, CNT, OUT);
}

// ys/yo fused: grid (512, 4): y&1 = co-half, y>>1 = s/o select.
__global__ void __launch_bounds__(256, 2) ysyo_kernel(
    const float* __restrict__ obj_maps,
    const __half* __restrict__ was, const __half* __restrict__ wao,
    float* __restrict__ ys, float* __restrict__ yo)
{
    const __half* W = ((blockIdx.y >> 1) == 0) ? was : wao;
    float* OUT      = ((blockIdx.y >> 1) == 0) ? ys  : yo;
    tconv_body<64, 3, 6>(blockIdx.x, blockIdx.y & 1, obj_maps, nullptr, W,
                         nullptr, nullptr, OUT);
}

// ===========================================================================
// Launch
// ===========================================================================
extern "C" void kernel_launch(void* const* d_in, const int* in_sizes, int n_in,
                              void* d_out, int out_size)
{
    const float* obj_maps = (const float*)d_in[0];
    const float* pred     = (const float*)d_in[1];
    const int*   edges    = (const int*)  d_in[2];
    const float* w1a = (const float*)d_in[4];
    const float* w1b = (const float*)d_in[6];
    const float* b1b = (const float*)d_in[7];
    const float* w2a = (const float*)d_in[8];
    const float* w2b = (const float*)d_in[10];
    const float* woa = (const float*)d_in[12];
    const float* wob = (const float*)d_in[14];

    float* out_obj = (float*)d_out;
    float* out_p   = out_obj + (size_t)O_N * HID * HW;

    float *t1, *ys, *yo, *T1s, *T1o, *pooled, *u, *v, *yp, *wc, *cnt;
    cudaGetSymbolAddress((void**)&t1,     g_t1);
    cudaGetSymbolAddress((void**)&ys,     g_ys);
    cudaGetSymbolAddress((void**)&yo,     g_yo);
    cudaGetSymbolAddress((void**)&T1s,    g_T1s);
    cudaGetSymbolAddress((void**)&T1o,    g_T1o);
    cudaGetSymbolAddress((void**)&pooled, g_pooled);
    cudaGetSymbolAddress((void**)&u,      g_u);
    cudaGetSymbolAddress((void**)&v,      g_v);
    cudaGetSymbolAddress((void**)&yp,     g_yp);
    cudaGetSymbolAddress((void**)&wc,     g_wc);
    cudaGetSymbolAddress((void**)&cnt,    g_cnt);

    __half *was, *wao, *w1bp, *w1bso, *w2ah, *w2bh, *woah, *wobh;
    cudaGetSymbolAddress((void**)&was,   g_was);
    cudaGetSymbolAddress((void**)&wao,   g_wao);
    cudaGetSymbolAddress((void**)&w1bp,  g_w1bp);
    cudaGetSymbolAddress((void**)&w1bso, g_w1bso);
    cudaGetSymbolAddress((void**)&w2ah,  g_w2a);
    cudaGetSymbolAddress((void**)&w2bh,  g_w2b);
    cudaGetSymbolAddress((void**)&woah,  g_woa);
    cudaGetSymbolAddress((void**)&wobh,  g_wob);

    cudaFuncSetAttribute(ysyo_kernel,    cudaFuncAttributeMaxDynamicSharedMemorySize, SMEM_SZ);
    cudaFuncSetAttribute(tconv<64,3,2>,  cudaFuncAttributeMaxDynamicSharedMemorySize, SMEM_SZ);
    cudaFuncSetAttribute(tconv<128,3,2>, cudaFuncAttributeMaxDynamicSharedMemorySize, SMEM_SZ);
    cudaFuncSetAttribute(tconv<256,3,5>, cudaFuncAttributeMaxDynamicSharedMemorySize, SMEM_SZ);
    cudaFuncSetAttribute(tconv<128,1,2>, cudaFuncAttributeMaxDynamicSharedMemorySize, SMEM_SZ);
    cudaFuncSetAttribute(tconv<128,1,3>, cudaFuncAttributeMaxDynamicSharedMemorySize, SMEM_SZ);
    cudaFuncSetAttribute(combine2,       cudaFuncAttributeMaxDynamicSharedMemorySize, CB2_SMEM);

    cudaStream_t s1 = g_res.s1, s2 = g_res.s2;
    cudaEvent_t  eP = g_res.eP, eW = g_res.eW, eC = g_res.eC,
                 e1 = g_res.e1, e2 = g_res.e2;

    // ---- mega weight prep ----
    PrepTable tab;
    tab.d[0] = { w1a, was,     0,   0, 192, 9, 1, 0, 1 };
    tab.d[1] = { w1a, wao,     0, 128, 192, 9, 1, 0, 1 };
    tab.d[2] = { w1b, w1bp,  128,   0, 128, 9, 2, 0, 2 };
    tab.d[3] = { w1b, w1bso,   0,   0, 128, 9, 2, 0, 4 };
    tab.d[4] = { w1b, w1bso, 256,   0, 128, 9, 2, 2, 4 };
    tab.d[5] = { w2a, w2ah,    0,   0, 128, 9, 2, 0, 2 };
    tab.d[6] = { w2b, w2bh,    0,   0, 128, 1, 2, 0, 2 };
    tab.d[7] = { woa, woah,    0,   0,  64, 9, 1, 0, 1 };
    tab.d[8] = { wob, wobh,    0,   0, 128, 1, 2, 0, 2 };
    megaprep<<<dim3(64, 9), 256>>>(tab);
    cudaEventRecord(eP, 0);

    // Side branch s2: wc + yp under the ysyo conv
    cudaStreamWaitEvent(s2, eP, 0);
    wc_kernel<<<(9*128*64 + 255) / 256, 256, 0, s2>>>(w1a, wc);
    yp_kernel<<<T_N, 256, 0, s2>>>(pred, wc, yp);
    cudaEventRecord(eW, s2);

    // Side branch s1: v = block(obj_maps, woa); out_obj = block(v, wob) (WRITE)
    cudaStreamWaitEvent(s1, eP, 0);
    tconv<64,3,2><<<dim3(O_N,2), 256, SMEM_SZ, s1>>>(obj_maps, nullptr, woah, nullptr, nullptr, v);
    tconv<128,1,2><<<dim3(O_N,2), 256, SMEM_SZ, s1>>>(v, nullptr, wobh, nullptr, nullptr, out_obj);
    cudaEventRecord(e1, s1);

    // Main: ys|yo fused (x co-halves), then combine (needs yp)
    ysyo_kernel<<<dim3(O_N, 4), 256, SMEM_SZ>>>(obj_maps, was, wao, ys, yo);
    cudaStreamWaitEvent(0, eW, 0);
    combine2<<<dim3(T_N, 2), 256, CB2_SMEM>>>(ys, yo, yp, edges, t1);
    cudaEventRecord(eC, 0);

    // Side branch s2: new_p conv -> out_p
    cudaStreamWaitEvent(s2, eC, 0);
    tconv<128,3,2><<<dim3(T_N,2), 256, SMEM_SZ, s2>>>(t1, nullptr, w1bp, nullptr, nullptr, out_p);
    cudaEventRecord(e2, s2);

    // Main: pool -> pooled conv -> u -> out_obj += block(u, w2b)
    pool_t1<<<O_N, 256>>>(t1, edges, T1s, T1o, cnt);
    tconv<256,3,5><<<dim3(O_N,2), 256, SMEM_SZ>>>(T1s, T1o, w1bso, b1b, cnt, pooled);
    tconv<128,3,2><<<dim3(O_N,2), 256, SMEM_SZ>>>(pooled, nullptr, w2ah, nullptr, nullptr, u);
    cudaStreamWaitEvent(0, e1, 0);   // wob write must precede w2b add
    tconv<128,1,3><<<dim3(O_N,2), 256, SMEM_SZ>>>(u, nullptr, w2bh, nullptr, nullptr, out_obj);
    cudaStreamWaitEvent(0, e2, 0);   // join new_p branch before returning
}

// round 17
// speedup vs baseline: 1.4646x; 1.0245x over previous
#include <cuda_runtime.h>
#include <cuda_fp16.h>
#include <cstdint>

typedef unsigned long long u64;
typedef uint32_t u32;

// Problem constants
#define O_N   512
#define T_N   1024
#define HW    256     // 16x16
#define DIN   64
#define DP    64
#define HID   128
#define DOUT  128

// ===========================================================================
// Side streams/events: created ONCE at program load (static initializer).
// ===========================================================================
struct SideRes {
    cudaStream_t s1, s2;
    cudaEvent_t  eP, eW, eY, eC, e1, e2;
    SideRes() {
        cudaStreamCreateWithFlags(&s1, cudaStreamNonBlocking);
        cudaStreamCreateWithFlags(&s2, cudaStreamNonBlocking);
        cudaEventCreateWithFlags(&eP, cudaEventDisableTiming);
        cudaEventCreateWithFlags(&eW, cudaEventDisableTiming);
        cudaEventCreateWithFlags(&eY, cudaEventDisableTiming);
        cudaEventCreateWithFlags(&eC, cudaEventDisableTiming);
        cudaEventCreateWithFlags(&e1, cudaEventDisableTiming);
        cudaEventCreateWithFlags(&e2, cudaEventDisableTiming);
    }
};
static SideRes g_res;

// ===========================================================================
// mma.sync / ldmatrix / cp.async helpers
// ===========================================================================
__device__ __forceinline__ u32 smem_u32(const void* p) {
    u32 a;
    asm("{ .reg .u64 t; cvta.to.shared.u64 t, %1; cvt.u32.u64 %0, t; }" : "=r"(a) : "l"(p));
    return a;
}
__device__ __forceinline__ void ldsm4(u32* r, u32 addr) {
    asm volatile("ldmatrix.sync.aligned.m8n8.x4.shared.b16 {%0,%1,%2,%3}, [%4];"
                 : "=r"(r[0]), "=r"(r[1]), "=r"(r[2]), "=r"(r[3]) : "r"(addr));
}
__device__ __forceinline__ void mma16816(float* d, const u32* a, const u32* b) {
    asm volatile(
        "mma.sync.aligned.m16n8k16.row.col.f32.f16.f16.f32 "
        "{%0,%1,%2,%3}, {%4,%5,%6,%7}, {%8,%9}, {%0,%1,%2,%3};"
        : "+f"(d[0]), "+f"(d[1]), "+f"(d[2]), "+f"(d[3])
        : "r"(a[0]), "r"(a[1]), "r"(a[2]), "r"(a[3]), "r"(b[0]), "r"(b[1]));
}
__device__ __forceinline__ void cpa16(u32 dst, const void* src) {
    asm volatile("cp.async.cg.shared.global [%0], [%1], 16;" :: "r"(dst), "l"(src));
}
#define CP_COMMIT() asm volatile("cp.async.commit_group;" ::: "memory")
#define CP_WAIT0()  asm volatile("cp.async.wait_group 0;" ::: "memory")

// ===========================================================================
// Scratch buffers (fp32, [n][ch][px] layout)
// ===========================================================================
__device__ float g_t1 [(size_t)T_N * HID * HW];
__device__ float g_ys [(size_t)O_N * HID * HW];
__device__ float g_yo [(size_t)O_N * HID * HW];
__device__ float g_T1s[(size_t)O_N * HID * HW];
__device__ float g_T1o[(size_t)O_N * HID * HW];
__device__ float g_pooled[(size_t)O_N * HID * HW];
__device__ float g_u  [(size_t)O_N * HID * HW];
__device__ float g_v  [(size_t)O_N * HID * HW];
__device__ float g_yp [(size_t)T_N * HID * 9];
__device__ float g_wc [9 * HID * 64];
__device__ float g_cnt[2 * O_N];

// fp16 weights, padded tile layout (tile = tap*NCHUNK+chunk; [co][72 halfs])
__device__ __align__(16) __half g_was  [ 82944];
__device__ __align__(16) __half g_wao  [ 82944];
__device__ __align__(16) __half g_w1bp [165888];
__device__ __align__(16) __half g_w1bso[331776];
__device__ __align__(16) __half g_w2a  [165888];
__device__ __align__(16) __half g_w2b  [ 18432];
__device__ __align__(16) __half g_woa  [ 82944];
__device__ __align__(16) __half g_wob  [ 18432];

// ===========================================================================
// Mega weight prep
// ===========================================================================
struct PrepDesc {
    const float* W;
    __half* H;
    int co_off, ci_off, cin, ks2, nch, dst_ch0, dst_nch;
};
struct PrepTable { PrepDesc d[9]; };

__global__ void __launch_bounds__(256) megaprep(PrepTable tab)
{
    PrepDesc d = tab.d[blockIdx.y];
    const int per_co = d.ks2 * d.nch * 72;
    const int total  = 128 * per_co;
    for (int idx = blockIdx.x * blockDim.x + threadIdx.x; idx < total;
         idx += gridDim.x * blockDim.x) {
        int co   = idx / per_co;
        int rem  = idx % per_co;
        int t    = rem / (d.nch * 72);
        int rem2 = rem % (d.nch * 72);
        int ch   = rem2 / 72;
        int c72  = rem2 % 72;
        float v = 0.f;
        if (c72 < 64)
            v = d.W[((size_t)(co + d.co_off) * d.cin + d.ci_off + ch * 64 + c72) * d.ks2 + t];
        int tile = t * d.dst_nch + d.dst_ch0 + ch;
        d.H[(size_t)tile * 9216 + (size_t)co * 72 + c72] = __float2half_rn(v);
    }
}

// Wc[cls][co][ci]
__global__ void wc_kernel(const float* __restrict__ w1a, float* __restrict__ Wc) {
    int idx = blockIdx.x * blockDim.x + threadIdx.x;
    if (idx >= 9 * 128 * 64) return;
    int cls = idx / (128 * 64);
    int co  = (idx / 64) % 128;
    int ci  = idx % 64;
    int cy = cls / 3, cx = cls % 3;
    float sum = 0.f;
    for (int ky = 0; ky < 3; ky++) {
        if ((cy == 0 && ky == 0) || (cy == 2 && ky == 2)) continue;
        for (int kx = 0; kx < 3; kx++) {
            if ((cx == 0 && kx == 0) || (cx == 2 && kx == 2)) continue;
            sum += w1a[((size_t)co * 192 + 64 + ci) * 9 + ky * 3 + kx];
        }
    }
    Wc[idx] = sum;
}

// yp[t][co*9+cls]
__global__ void __launch_bounds__(256) yp_kernel(
    const float* __restrict__ pred, const float* __restrict__ Wc,
    float* __restrict__ yp)
{
    __shared__ float sp[64];
    int t = blockIdx.x;
    int tid = threadIdx.x;
    if (tid < 64) sp[tid] = pred[(size_t)t * DP + tid];
    __syncthreads();
    for (int i = tid; i < 128 * 9; i += 256) {
        int co = i / 9, cls = i % 9;
        const float* wc = Wc + ((size_t)cls * 128 + co) * 64;
        float sum = 0.f;
#pragma unroll 16
        for (int ci = 0; ci < 64; ci++) sum += sp[ci] * wc[ci];
        yp[(size_t)t * 1152 + i] = sum;
    }
}

// ===========================================================================
// Combine v2 (channel-split, smem-cached): t1 = lrelu(inorm(ys[s]+yp+yo[o]))
// ===========================================================================
#define CB2_VAL   0
#define CB2_YP    16384
#define CB2_SUM   (16384 + 576)
#define CB2_SSQ   (16384 + 576 + 512)
#define CB2_MEAN  (16384 + 576 + 1024)
#define CB2_SCL   (16384 + 576 + 1024 + 64)
#define CB2_SMEM  ((16384 + 576 + 1024 + 128) * 4)

__global__ void __launch_bounds__(256) combine2(
    const float* __restrict__ ys, const float* __restrict__ yo,
    const float* __restrict__ yp, const int* __restrict__ edges,
    float* __restrict__ t1)
{
    extern __shared__ float sm[];
    float* s_val  = sm + CB2_VAL;
    float* s_yp   = sm + CB2_YP;
    float* s_sum  = sm + CB2_SUM;
    float* s_ssq  = sm + CB2_SSQ;
    float* s_mean = sm + CB2_MEAN;
    float* s_scl  = sm + CB2_SCL;

    const int t   = blockIdx.x;
    const int hh  = blockIdx.y;
    const int tid = threadIdx.x;
    const int lane = tid & 31;
    const int w    = tid >> 5;
    const int s = edges[2 * t], o = edges[2 * t + 1];

    for (int i = tid; i < 576; i += 256)
        s_yp[i] = yp[(size_t)t * 1152 + hh * 576 + i];
    __syncthreads();

    const int px = tid;
    const int y = px >> 4, x = px & 15;
    const int cy = (y == 0) ? 0 : ((y == 15) ? 2 : 1);
    const int cx = (x == 0) ? 0 : ((x == 15) ? 2 : 1);
    const int cls = cy * 3 + cx;
    const float* ysb = ys + ((size_t)s * HID + hh * 64) * HW + px;
    const float* yob = yo + ((size_t)o * HID + hh * 64) * HW + px;

    for (int ch = 0; ch < 64; ch++) {
        float val = ysb[ch * HW] + yob[ch * HW] + s_yp[ch * 9 + cls];
        s_val[ch * 256 + px] = val;
        float sm_ = val, sq = val * val;
#pragma unroll
        for (int off = 16; off > 0; off >>= 1) {
            sm_ += __shfl_xor_sync(0xffffffffu, sm_, off);
            sq  += __shfl_xor_sync(0xffffffffu, sq,  off);
        }
        if (lane == 0) { s_sum[ch * 8 + w] = sm_; s_ssq[ch * 8 + w] = sq; }
    }
    __syncthreads();
    if (tid < 64) {
        float S = 0.f, SS = 0.f;
#pragma unroll
        for (int k = 0; k < 8; k++) { S += s_sum[tid * 8 + k]; SS += s_ssq[tid * 8 + k]; }
        float m = S * (1.f / 256.f);
        float var = SS * (1.f / 256.f) - m * m;
        s_mean[tid] = m;
        s_scl[tid]  = rsqrtf(var + 1e-5f);
    }
    __syncthreads();
    float* dst = t1 + ((size_t)t * HID + hh * 64) * HW + px;
    for (int ch = 0; ch < 64; ch++) {
        float vv = (s_val[ch * 256 + px] - s_mean[ch]) * s_scl[ch];
        dst[ch * HW] = (vv >= 0.f) ? vv : 0.1f * vv;
    }
}

// ===========================================================================
// Deterministic segment SUM of t1 over s-edges and o-edges, plus counts.
// ===========================================================================
__global__ void __launch_bounds__(256) pool_t1(
    const float* __restrict__ t1, const int* __restrict__ edges,
    float* __restrict__ T1s, float* __restrict__ T1o, float* __restrict__ CNT)
{
    __shared__ int es[T_N], eo[T_N];
    __shared__ int listS[T_N], listO[T_N];
    __shared__ int cS, cO;

    const int o   = blockIdx.x;
    const int tid = threadIdx.x;

    for (int i = tid; i < T_N; i += 256) {
        es[i] = edges[2 * i];
        eo[i] = edges[2 * i + 1];
    }
    __syncthreads();
    if (tid == 0) { int c = 0; for (int t = 0; t < T_N; t++) if (es[t] == o) listS[c++] = t; cS = c; }
    if (tid == 32){ int c = 0; for (int t = 0; t < T_N; t++) if (eo[t] == o) listO[c++] = t; cO = c; }
    __syncthreads();
    const int cs = cS, co = cO;

    for (int cb = 0; cb < 4; cb++) {
        float accS[32], accO[32];
#pragma unroll
        for (int j = 0; j < 32; j++) { accS[j] = 0.f; accO[j] = 0.f; }
        for (int m = 0; m < cs; m++) {
            const float* src = t1 + ((size_t)listS[m] * HID + cb * 32) * HW + tid;
#pragma unroll
            for (int j = 0; j < 32; j++) accS[j] += src[(size_t)j * HW];
        }
        for (int m = 0; m < co; m++) {
            const float* src = t1 + ((size_t)listO[m] * HID + cb * 32) * HW + tid;
#pragma unroll
            for (int j = 0; j < 32; j++) accO[j] += src[(size_t)j * HW];
        }
#pragma unroll
        for (int j = 0; j < 32; j++) {
            T1s[((size_t)o * HID + cb * 32 + j) * HW + tid] = accS[j];
            T1o[((size_t)o * HID + cb * 32 + j) * HW + tid] = accO[j];
        }
    }
    if (tid == 0) { CNT[o] = (float)cs; CNT[O_N + o] = (float)co; }
}

// ===========================================================================
// tconv body: single-term fp16 implicit-GEMM conv, M-SPLIT (M=64, N=256).
// A tiles in GROUPS of GS taps (GS=3 for 3x3), double-buffered.
// X staging uses STS.64 (4 channels/thread). rt_inorm: runtime inorm flag
// (used only by VARIANT 6, letting ys/yo/v share one instantiation).
// 256 thr / 8 warps; 2 CTAs/SM.
// VARIANT: 2 inorm->OUT | 3 inorm add->OUT | 5 dual-input pooled conv | 6 raw/rt
// ===========================================================================
#define OFF_A0   0                        // GSmax(3) * 9216 = 27648
#define OFF_A1   27648
#define OFF_XH   55296
#define OFF_SUM  92304                    // 55296 + 257*144
#define OFF_SSQ  (92304 + 2048)
#define SMEM_SZ  (92304 + 4096)

template<int CIN, int KS, int VARIANT>
__device__ __forceinline__ void tconv_body(
    int n, int mhalf,
    const float* __restrict__ X,
    const float* __restrict__ X2,
    const __half* __restrict__ WH,
    const float* __restrict__ BIAS,
    const float* __restrict__ CNT,
    float* __restrict__ OUT,
    bool rt_inorm = false)
{
    constexpr int KS2 = KS * KS;
    constexpr int NCHUNK = CIN / 64;
    constexpr int GS = (KS == 3) ? 3 : 1;      // taps per group
    constexpr int NG = KS2 / GS;               // groups per chunk
    extern __shared__ __align__(16) char smem[];
    const u32 sb = smem_u32(smem);

    const int tid  = threadIdx.x;
    const int lane = tid & 31;
    const int wid  = tid >> 5;
    const int wn   = wid;                 // 0..7 -> N 32-slice

    // zero row (pixel index 256) for OOB taps
    if (tid < 36)
        *(u32*)(smem + OFF_XH + 256 * 144 + tid * 4) = 0u;

    float acc[4][4][4];
#pragma unroll
    for (int a = 0; a < 4; a++)
#pragma unroll
        for (int b = 0; b < 4; b++)
#pragma unroll
            for (int c = 0; c < 4; c++) acc[a][b][c] = 0.f;

    const int nl    = (lane & 7) + ((lane >> 4) & 1) * 8;
    const int khalf = (lane >> 3) & 1;
    const int kha   = (lane >> 4) & 1;
    const u32 aOff  = (u32)((lane & 15) * 144 + kha * 16);
    const size_t wsub = (size_t)mhalf * 4608;   // co-half offset within a tile (halfs)

    for (int chunk = 0; chunk < NCHUNK; chunk++) {
        if (chunk) __syncthreads();   // prev chunk compute done (buffers reusable)

        // ---- prefetch group 0 (GS tap half-tiles, 576 int4 each) ----
        for (int i = tid; i < GS * 576; i += 256) {
            int k = i / 576;
            int j = i - k * 576;
            const int4* s = (const int4*)(WH + (size_t)(k * NCHUNK + chunk) * 9216 + wsub) + j;
            cpa16(sb + OFF_A0 + k * 9216 + j * 16, s);
        }
        CP_COMMIT();

        // ---- stage X chunk -> fp16 plane [px][64ci], STS.64 (4ch/thread) ----
        for (int i = tid; i < 16 * 256; i += 256) {
            int cc = (i >> 8) * 4;
            int p  = i & 255;
            const float* s;
            if (VARIANT == 5) {
                s = (chunk < 2)
                        ? X  + ((size_t)n * 128 + chunk * 64 + cc) * HW + p
                        : X2 + ((size_t)n * 128 + (chunk - 2) * 64 + cc) * HW + p;
            } else {
                s = X + ((size_t)n * CIN + chunk * 64 + cc) * HW + p;
            }
            float v0 = s[0], v1 = s[HW], v2 = s[2 * HW], v3 = s[3 * HW];
            __half2 h01(__float2half_rn(v0), __float2half_rn(v1));
            __half2 h23(__float2half_rn(v2), __float2half_rn(v3));
            u32 w01 = *(u32*)&h01;
            u32 w23 = *(u32*)&h23;
            u64 pk = (u64)w01 | ((u64)w23 << 32);
            *(u64*)(smem + OFF_XH + p * 144 + cc * 2) = pk;
        }

        CP_WAIT0();
        __syncthreads();   // group-0 A + X plane ready

        int buf = 0;
        for (int g = 0; g < NG; g++) {
            // prefetch next group into the other buffer
            if (g + 1 < NG) {
                u32 d = sb + (buf ? OFF_A0 : OFF_A1);
                for (int i = tid; i < GS * 576; i += 256) {
                    int k = i / 576;
                    int j = i - k * 576;
                    int tap = (g + 1) * GS + k;
                    const int4* s = (const int4*)(WH + (size_t)(tap * NCHUNK + chunk) * 9216 + wsub) + j;
                    cpa16(d + k * 9216 + j * 16, s);
                }
                CP_COMMIT();
            }

            const u32 abase = sb + (buf ? OFF_A1 : OFF_A0);
            // ---- compute GS taps back-to-back, no barriers ----
#pragma unroll
            for (int k = 0; k < GS; k++) {
                const int tap = g * GS + k;
                const int dy = (KS == 3) ? (tap / 3 - 1) : 0;
                const int dx = (KS == 3) ? (tap % 3 - 1) : 0;
                u32 bBH[2];
#pragma unroll
                for (int nb = 0; nb < 2; nb++) {
                    int p = wn * 32 + nb * 16 + nl;
                    int y = p >> 4, x = p & 15;
                    int ys_ = y + dy, xs = x + dx;
                    u32 row = (((unsigned)ys_ < 16u) && ((unsigned)xs < 16u))
                                  ? (u32)(ys_ * 16 + xs) : 256u;
                    bBH[nb] = sb + OFF_XH + row * 144 + khalf * 16;
                }
                const u32 aB = abase + k * 9216 + aOff;

#pragma unroll
                for (int ks = 0; ks < 4; ks++) {
                    const u32 kb = ks * 32;
                    u32 bh[2][4];
                    ldsm4(bh[0], bBH[0] + kb);
                    ldsm4(bh[1], bBH[1] + kb);
                    u32 a[4][4];
#pragma unroll
                    for (int mt = 0; mt < 4; mt++) ldsm4(a[mt], aB + mt * 2304 + kb);
#pragma unroll
                    for (int mt = 0; mt < 4; mt++)
#pragma unroll
                        for (int nf = 0; nf < 4; nf++)
                            mma16816(acc[mt][nf], a[mt], &bh[nf >> 1][(nf & 1) * 2]);
                }
            }

            if (g + 1 < NG) {
                CP_WAIT0();
                __syncthreads();
            }
            buf ^= 1;
        }
    }

    // ======================= epilogue =======================
    const bool do_inorm = (VARIANT == 2 || VARIANT == 3) ||
                          (VARIANT == 6 && rt_inorm);
    const int q    = lane >> 2;
    const int csub = lane & 3;

    float* s_sum = (float*)(smem + OFF_SUM);   // [64][8]
    float* s_ssq = (float*)(smem + OFF_SSQ);

    float mean[4][2], scl[4][2], extra[4][2];
    float inv5 = 1.f;

    __syncthreads();

    if (do_inorm) {
#pragma unroll
        for (int mt = 0; mt < 4; mt++)
#pragma unroll
            for (int h = 0; h < 2; h++) {
                float sm = 0.f, sq = 0.f;
#pragma unroll
                for (int nf = 0; nf < 4; nf++) {
                    float v = acc[mt][nf][2 * h], w = acc[mt][nf][2 * h + 1];
                    sm += v + w;
                    sq += v * v + w * w;
                }
                sm += __shfl_xor_sync(0xffffffffu, sm, 1);
                sq += __shfl_xor_sync(0xffffffffu, sq, 1);
                sm += __shfl_xor_sync(0xffffffffu, sm, 2);
                sq += __shfl_xor_sync(0xffffffffu, sq, 2);
                if (csub == 0) {
                    int r = mt * 16 + q + h * 8;
                    s_sum[r * 8 + wn] = sm;
                    s_ssq[r * 8 + wn] = sq;
                }
            }
        __syncthreads();
#pragma unroll
        for (int mt = 0; mt < 4; mt++)
#pragma unroll
            for (int h = 0; h < 2; h++) {
                int r = mt * 16 + q + h * 8;
                float S = 0.f, SS = 0.f;
#pragma unroll
                for (int w = 0; w < 8; w++) { S += s_sum[r * 8 + w]; SS += s_ssq[r * 8 + w]; }
                float m = S * (1.f / 256.f);
                float var = SS * (1.f / 256.f) - m * m;
                mean[mt][h] = m;
                scl[mt][h]  = rsqrtf(var + 1e-5f);
            }
    } else if (VARIANT == 5) {
        float cs = CNT[n], cf = CNT[O_N + n];
        inv5 = 1.f / fmaxf(cs + cf, 1.f);
#pragma unroll
        for (int mt = 0; mt < 4; mt++)
#pragma unroll
            for (int h = 0; h < 2; h++) {
                int gco = mhalf * 64 + mt * 16 + q + h * 8;
                extra[mt][h] = cs * BIAS[gco] + cf * BIAS[256 + gco];
            }
    }

    float* dst = OUT + (size_t)n * HID * HW;

#pragma unroll
    for (int mt = 0; mt < 4; mt++)
#pragma unroll
        for (int h = 0; h < 2; h++) {
            int gco = mhalf * 64 + mt * 16 + q + h * 8;
            float* rowp = dst + (size_t)gco * HW;
#pragma unroll
            for (int nf = 0; nf < 4; nf++) {
                int c = wn * 32 + nf * 8 + csub * 2;
                float v0 = acc[mt][nf][2 * h];
                float v1 = acc[mt][nf][2 * h + 1];
                if (do_inorm) {
                    v0 = (v0 - mean[mt][h]) * scl[mt][h];
                    v1 = (v1 - mean[mt][h]) * scl[mt][h];
                    v0 = (v0 >= 0.f) ? v0 : 0.1f * v0;
                    v1 = (v1 >= 0.f) ? v1 : 0.1f * v1;
                } else if (VARIANT == 5) {
                    v0 = (v0 + extra[mt][h]) * inv5;
                    v1 = (v1 + extra[mt][h]) * inv5;
                }
                float2* p2 = (float2*)(rowp + c);
                if (VARIANT == 3) {
                    float2 old = *p2;
                    *p2 = make_float2(old.x + v0, old.y + v1);
                } else {
                    *p2 = make_float2(v0, v1);
                }
            }
        }
}

// Generic wrapper: grid (n, 2) -> (image, co-half)
template<int CIN, int KS, int VARIANT>
__global__ void __launch_bounds__(256, 2) tconv(
    const float* __restrict__ X,
    const float* __restrict__ X2,
    const __half* __restrict__ WH,
    const float* __restrict__ BIAS,
    const float* __restrict__ CNT,
    float* __restrict__ OUT)
{
    tconv_body<CIN, KS, VARIANT>(blockIdx.x, blockIdx.y, X, X2, WH, BIAS, CNT, OUT);
}

// ys/yo/v fused: grid (512, 6): y&1 = co-half, y>>1 = {ys, yo, v(inorm)}.
__global__ void __launch_bounds__(256, 2) ysyov_kernel(
    const float* __restrict__ obj_maps,
    const __half* __restrict__ was, const __half* __restrict__ wao,
    const __half* __restrict__ woa,
    float* __restrict__ ys, float* __restrict__ yo, float* __restrict__ v)
{
    const int sel = blockIdx.y >> 1;
    const __half* W = (sel == 0) ? was : ((sel == 1) ? wao : woa);
    float* OUT      = (sel == 0) ? ys  : ((sel == 1) ? yo  : v);
    tconv_body<64, 3, 6>(blockIdx.x, blockIdx.y & 1, obj_maps, nullptr, W,
                         nullptr, nullptr, OUT, sel == 2);
}

// ===========================================================================
// Launch
// ===========================================================================
extern "C" void kernel_launch(void* const* d_in, const int* in_sizes, int n_in,
                              void* d_out, int out_size)
{
    const float* obj_maps = (const float*)d_in[0];
    const float* pred     = (const float*)d_in[1];
    const int*   edges    = (const int*)  d_in[2];
    const float* w1a = (const float*)d_in[4];
    const float* w1b = (const float*)d_in[6];
    const float* b1b = (const float*)d_in[7];
    const float* w2a = (const float*)d_in[8];
    const float* w2b = (const float*)d_in[10];
    const float* woa = (const float*)d_in[12];
    const float* wob = (const float*)d_in[14];

    float* out_obj = (float*)d_out;
    float* out_p   = out_obj + (size_t)O_N * HID * HW;

    float *t1, *ys, *yo, *T1s, *T1o, *pooled, *u, *v, *yp, *wc, *cnt;
    cudaGetSymbolAddress((void**)&t1,     g_t1);
    cudaGetSymbolAddress((void**)&ys,     g_ys);
    cudaGetSymbolAddress((void**)&yo,     g_yo);
    cudaGetSymbolAddress((void**)&T1s,    g_T1s);
    cudaGetSymbolAddress((void**)&T1o,    g_T1o);
    cudaGetSymbolAddress((void**)&pooled, g_pooled);
    cudaGetSymbolAddress((void**)&u,      g_u);
    cudaGetSymbolAddress((void**)&v,      g_v);
    cudaGetSymbolAddress((void**)&yp,     g_yp);
    cudaGetSymbolAddress((void**)&wc,     g_wc);
    cudaGetSymbolAddress((void**)&cnt,    g_cnt);

    __half *was, *wao, *w1bp, *w1bso, *w2ah, *w2bh, *woah, *wobh;
    cudaGetSymbolAddress((void**)&was,   g_was);
    cudaGetSymbolAddress((void**)&wao,   g_wao);
    cudaGetSymbolAddress((void**)&w1bp,  g_w1bp);
    cudaGetSymbolAddress((void**)&w1bso, g_w1bso);
    cudaGetSymbolAddress((void**)&w2ah,  g_w2a);
    cudaGetSymbolAddress((void**)&w2bh,  g_w2b);
    cudaGetSymbolAddress((void**)&woah,  g_woa);
    cudaGetSymbolAddress((void**)&wobh,  g_wob);

    cudaFuncSetAttribute(ysyov_kernel,   cudaFuncAttributeMaxDynamicSharedMemorySize, SMEM_SZ);
    cudaFuncSetAttribute(tconv<128,3,2>, cudaFuncAttributeMaxDynamicSharedMemorySize, SMEM_SZ);
    cudaFuncSetAttribute(tconv<256,3,5>, cudaFuncAttributeMaxDynamicSharedMemorySize, SMEM_SZ);
    cudaFuncSetAttribute(tconv<128,1,2>, cudaFuncAttributeMaxDynamicSharedMemorySize, SMEM_SZ);
    cudaFuncSetAttribute(tconv<128,1,3>, cudaFuncAttributeMaxDynamicSharedMemorySize, SMEM_SZ);
    cudaFuncSetAttribute(combine2,       cudaFuncAttributeMaxDynamicSharedMemorySize, CB2_SMEM);

    cudaStream_t s1 = g_res.s1, s2 = g_res.s2;
    cudaEvent_t  eP = g_res.eP, eW = g_res.eW, eY = g_res.eY, eC = g_res.eC,
                 e1 = g_res.e1, e2 = g_res.e2;

    // ---- mega weight prep ----
    PrepTable tab;
    tab.d[0] = { w1a, was,     0,   0, 192, 9, 1, 0, 1 };
    tab.d[1] = { w1a, wao,     0, 128, 192, 9, 1, 0, 1 };
    tab.d[2] = { w1b, w1bp,  128,   0, 128, 9, 2, 0, 2 };
    tab.d[3] = { w1b, w1bso,   0,   0, 128, 9, 2, 0, 4 };
    tab.d[4] = { w1b, w1bso, 256,   0, 128, 9, 2, 2, 4 };
    tab.d[5] = { w2a, w2ah,    0,   0, 128, 9, 2, 0, 2 };
    tab.d[6] = { w2b, w2bh,    0,   0, 128, 1, 2, 0, 2 };
    tab.d[7] = { woa, woah,    0,   0,  64, 9, 1, 0, 1 };
    tab.d[8] = { wob, wobh,    0,   0, 128, 1, 2, 0, 2 };
    megaprep<<<dim3(64, 9), 256>>>(tab);
    cudaEventRecord(eP, 0);

    // Side branch s2: wc + yp under the ysyov conv
    cudaStreamWaitEvent(s2, eP, 0);
    wc_kernel<<<(9*128*64 + 255) / 256, 256, 0, s2>>>(w1a, wc);
    yp_kernel<<<T_N, 256, 0, s2>>>(pred, wc, yp);
    cudaEventRecord(eW, s2);

    // Main: ys | yo | v fused (6 y-slices)
    ysyov_kernel<<<dim3(O_N, 6), 256, SMEM_SZ>>>(obj_maps, was, wao, woah, ys, yo, v);
    cudaEventRecord(eY, 0);

    // Side branch s1: out_obj = block(v, wob) (WRITE), overlaps combine
    cudaStreamWaitEvent(s1, eY, 0);
    tconv<128,1,2><<<dim3(O_N,2), 256, SMEM_SZ, s1>>>(v, nullptr, wobh, nullptr, nullptr, out_obj);
    cudaEventRecord(e1, s1);

    // Main: combine (needs yp)
    cudaStreamWaitEvent(0, eW, 0);
    combine2<<<dim3(T_N, 2), 256, CB2_SMEM>>>(ys, yo, yp, edges, t1);
    cudaEventRecord(eC, 0);

    // Side branch s2: new_p conv -> out_p
    cudaStreamWaitEvent(s2, eC, 0);
    tconv<128,3,2><<<dim3(T_N,2), 256, SMEM_SZ, s2>>>(t1, nullptr, w1bp, nullptr, nullptr, out_p);
    cudaEventRecord(e2, s2);

    // Main: pool -> pooled conv -> u -> out_obj += block(u, w2b)
    pool_t1<<<O_N, 256>>>(t1, edges, T1s, T1o, cnt);
    tconv<256,3,5><<<dim3(O_N,2), 256, SMEM_SZ>>>(T1s, T1o, w1bso, b1b, cnt, pooled);
    tconv<128,3,2><<<dim3(O_N,2), 256, SMEM_SZ>>>(pooled, nullptr, w2ah, nullptr, nullptr, u);
    cudaStreamWaitEvent(0, e1, 0);   // wob write must precede w2b add
    tconv<128,1,3><<<dim3(O_N,2), 256, SMEM_SZ>>>(u, nullptr, w2bh, nullptr, nullptr, out_obj);
    cudaStreamWaitEvent(0, e2, 0);   // join new_p branch before returning
}